// round 10
// baseline (speedup 1.0000x reference)
#include <cuda_runtime.h>
#include <cuda_fp16.h>
#include <cstdint>

// ---------------------------------------------------------------------------
// Problem dims
// ---------------------------------------------------------------------------
#define BSZ   16384
#define D1    1536    // gpe in / gpe out / gpi out
#define D2    3072    // gpi in (concat)
#define D3    512     // unit3
#define NACT  6

#define BM 128
#define BK 64
#define STAGES 4
#define NTHREADS 512

// ---------------------------------------------------------------------------
// Helpers (plain sm_103 ISA: cp.async + ldmatrix + mma.sync)
// ---------------------------------------------------------------------------
__device__ __forceinline__ uint32_t smem_u32(const void* p) {
    uint32_t a;
    asm("{ .reg .u64 t; cvta.to.shared.u64 t, %1; cvt.u32.u64 %0, t; }"
        : "=r"(a) : "l"(p));
    return a;
}

#define CP_ASYNC16(dst_u32, src_ptr) \
    asm volatile("cp.async.cg.shared.global [%0], [%1], 16;" \
                 :: "r"(dst_u32), "l"(src_ptr))
#define CP_COMMIT() asm volatile("cp.async.commit_group;")
#define CP_WAIT(n)  asm volatile("cp.async.wait_group %0;" :: "n"(n))

__device__ __forceinline__ void ldsm4(uint32_t* r, uint32_t a) {
    asm volatile("ldmatrix.sync.aligned.m8n8.x4.shared.b16 {%0,%1,%2,%3}, [%4];"
                 : "=r"(r[0]), "=r"(r[1]), "=r"(r[2]), "=r"(r[3]) : "r"(a));
}

__device__ __forceinline__ void mma16816(float* c, const uint32_t* a, const uint32_t* b) {
    asm volatile(
        "mma.sync.aligned.m16n8k16.row.col.f32.f16.f16.f32 "
        "{%0,%1,%2,%3}, {%4,%5,%6,%7}, {%8,%9}, {%0,%1,%2,%3};"
        : "+f"(c[0]), "+f"(c[1]), "+f"(c[2]), "+f"(c[3])
        : "r"(a[0]), "r"(a[1]), "r"(a[2]), "r"(a[3]), "r"(b[0]), "r"(b[1]));
}

#define SW128(o) ((uint32_t)(o) ^ ((((uint32_t)(o)) >> 3) & 0x70))

// ---------------------------------------------------------------------------
// Device scratch (no cudaMalloc allowed)
// ---------------------------------------------------------------------------
__device__ __align__(256) __half g_AC[(size_t)BSZ * D2];   // [B,3072] concat(x, gpe_out)
__device__ __align__(256) __half g_G [(size_t)BSZ * D1];   // gpi_out
__device__ __align__(256) __half g_H1[(size_t)BSZ * D3];
__device__ __align__(256) float  g_H2[(size_t)BSZ * D3];
__device__ __align__(256) __half g_Wg[(size_t)D1 * D1];    // [N][K]
__device__ __align__(256) __half g_Wi[(size_t)D1 * D2];
__device__ __align__(256) __half g_W1[(size_t)D3 * D1];
__device__ __align__(256) __half g_W2[(size_t)D3 * D3];

// ---------------------------------------------------------------------------
// Fused weight prep: tiled coalesced transpose (+ optional mask) -> fp16
// ---------------------------------------------------------------------------
__global__ void __launch_bounds__(256) prep_all(
    const float* W0, const float* M0, __half* O0, int K0, int N0,
    const float* W1p, const float* M1, __half* O1, int K1, int N1,
    const float* W2p, const float* M2, __half* O2, int K2, int N2,
    const float* W3p, const float* M3, __half* O3, int K3, int N3)
{
    const float* W; const float* mask; __half* out; int K, N;
    switch (blockIdx.z) {
        case 0:  W = W0;  mask = M0; out = O0; K = K0; N = N0; break;
        case 1:  W = W1p; mask = M1; out = O1; K = K1; N = N1; break;
        case 2:  W = W2p; mask = M2; out = O2; K = K2; N = N2; break;
        default: W = W3p; mask = M3; out = O3; K = K3; N = N3; break;
    }
    const int k0 = blockIdx.x * 32;
    const int n0 = blockIdx.y * 32;
    if (k0 >= K || n0 >= N) return;

    __shared__ float tile[32][33];
    const int tx = threadIdx.x & 31;
    const int ty = threadIdx.x >> 5;

    #pragma unroll
    for (int i = 0; i < 4; i++) {
        const int k = k0 + ty + i * 8;
        tile[ty + i * 8][tx] = W[(size_t)k * N + n0 + tx];
    }
    __syncthreads();

    #pragma unroll
    for (int i = 0; i < 4; i++) {
        const int n = n0 + ty + i * 8;
        const size_t o = (size_t)n * K + k0 + tx;
        float v = tile[tx][ty + i * 8];
        if (mask) v *= mask[o];
        out[o] = __float2half_rn(v);
    }
}

// x [B][1536] fp32 -> AC cols [0,1536) fp16 with row stride 3072
__global__ void split_x(const float* __restrict__ x, __half* __restrict__ o) {
    int i4 = blockIdx.x * 256 + threadIdx.x;
    const int quads_per_row = D1 / 4;                  // 384
    if (i4 >= BSZ * quads_per_row) return;
    int row = i4 / quads_per_row;
    int c4  = i4 - row * quads_per_row;
    float4 v = ((const float4*)x)[i4];
    size_t off = (size_t)row * D2 + c4 * 4;
    __half2 p0 = __floats2half2_rn(v.x, v.y);
    __half2 p1 = __floats2half2_rn(v.z, v.w);
    *(uint2*)(o + off) = make_uint2(*(uint32_t*)&p0, *(uint32_t*)&p1);
}

// ---------------------------------------------------------------------------
// fp16 GEMM, 512 threads, 16 warps in 4x4 grid; warp tile 32 x (BN/4).
// out[M,N] = A[M,K] @ Wt[N,K]^T + bias (fp32 acc)
// mode: 0 = store fp16, 1 = relu + store fp16, 2 = relu + store fp32
// ---------------------------------------------------------------------------
static constexpr int OFF_STAGE = 1024;     // bias lives in [0, BN*4)
static constexpr int ST_A = 0;             // A: 128 rows x 128B = 16KB

template<int BN_T>
__global__ void __launch_bounds__(NTHREADS, 1)
gemm_h(const __half* __restrict__ A, int lda,
       const __half* __restrict__ B, int ldb,
       const float* __restrict__ bias,
       __half* __restrict__ outH, float* __restrict__ outF,
       int ostride, int K, int mode)
{
    constexpr int WTN = BN_T / 4;          // warp tile N (4 N-warps)
    constexpr int NJ  = WTN / 8;           // n8-frags per warp
    constexpr int NB  = NJ / 2;            // B ldmatrix.x4 per ks per warp
    constexpr int BROWS = BN_T / 64;       // cp.async row-iters for B (512 thr)
    constexpr int STAGE_BYTES = 16384 + BN_T * 128;

    extern __shared__ char smem[];
    const uint32_t sb = smem_u32(smem);
    const int t = threadIdx.x, wid = t >> 5, lane = t & 31;
    const int wm = wid & 3, wn = wid >> 2;            // 4 x 4 warp grid
    const int m0 = blockIdx.x * BM;
    const int n0 = blockIdx.y * BN_T;

    if (t < BN_T) ((float*)smem)[t] = bias[n0 + t];

    const int chunk = t & 7;               // 16B chunk within 128B row
    const int rset  = t >> 3;              // 0..63

    auto load_stage = [&](int st, int kt) {
        const int k0 = kt * BK;
        const uint32_t stg = sb + OFF_STAGE + st * STAGE_BYTES;
        #pragma unroll
        for (int rr = 0; rr < 2; rr++) {
            const int row = rset + rr * 64;
            const uint32_t so = SW128(row * 128 + chunk * 16);
            CP_ASYNC16(stg + ST_A + so, A + (size_t)(m0 + row) * lda + k0 + chunk * 8);
        }
        #pragma unroll
        for (int rr = 0; rr < BROWS; rr++) {
            const int row = rset + rr * 64;
            const uint32_t so = SW128(row * 128 + chunk * 16);
            CP_ASYNC16(stg + 16384 + so, B + (size_t)(n0 + row) * ldb + k0 + chunk * 8);
        }
    };

    const int KT = K / BK;

    #pragma unroll
    for (int s = 0; s < STAGES - 1; s++) {
        if (s < KT) load_stage(s, s);
        CP_COMMIT();
    }

    float acc[2][NJ][4];
    #pragma unroll
    for (int a = 0; a < 2; a++)
        #pragma unroll
        for (int b = 0; b < NJ; b++)
            #pragma unroll
            for (int c = 0; c < 4; c++) acc[a][b][c] = 0.0f;

    // lane-invariant ldmatrix addressing
    const int rowA_l = wm * 32 + (lane & 15);
    const int kbA_l  = (lane & 16) ? 16 : 0;
    const int rowB_l = wn * WTN + (lane & 7) + ((lane & 16) ? 8 : 0);
    const int kbB_l  = (lane & 8) ? 16 : 0;

    for (int kt = 0; kt < KT; ++kt) {
        CP_WAIT(STAGES - 2);
        __syncthreads();
        // Single barrier per iter: the stage refilled below ((kt+3)%4) was
        // last read at iter kt-1, fully ordered by this barrier.
        if (kt + STAGES - 1 < KT) load_stage((kt + STAGES - 1) % STAGES, kt + STAGES - 1);
        CP_COMMIT();

        const uint32_t stg = sb + OFF_STAGE + (kt % STAGES) * STAGE_BYTES;
        #pragma unroll
        for (int ks = 0; ks < BK / 16; ks++) {
            uint32_t ah[2][4], bh[NB][4];
            const int kbA = ks * 32 + kbA_l;
            const int kbB = ks * 32 + kbB_l;
            #pragma unroll
            for (int mi = 0; mi < 2; mi++)
                ldsm4(ah[mi], stg + ST_A + SW128((rowA_l + mi * 16) * 128 + kbA));
            #pragma unroll
            for (int bj = 0; bj < NB; bj++)
                ldsm4(bh[bj], stg + 16384 + SW128((rowB_l + bj * 16) * 128 + kbB));
            #pragma unroll
            for (int mi = 0; mi < 2; mi++) {
                #pragma unroll
                for (int nj = 0; nj < NJ; nj++)
                    mma16816(acc[mi][nj], ah[mi], &bh[nj >> 1][(nj & 1) * 2]);
            }
        }
    }

    // -------------------- epilogue --------------------
    const float* sBias = (const float*)smem;
    const int q  = lane >> 2;
    const int p2 = 2 * (lane & 3);
    #pragma unroll
    for (int mi = 0; mi < 2; mi++) {
        #pragma unroll
        for (int nj = 0; nj < NJ; nj++) {
            const int cl = wn * WTN + nj * 8 + p2;
            const int r0 = m0 + wm * 32 + mi * 16 + q;
            const float bz0 = sBias[cl], bz1 = sBias[cl + 1];
            float v0 = acc[mi][nj][0] + bz0;
            float v1 = acc[mi][nj][1] + bz1;
            float v2 = acc[mi][nj][2] + bz0;
            float v3 = acc[mi][nj][3] + bz1;
            if (mode >= 1) {
                v0 = fmaxf(v0, 0.f); v1 = fmaxf(v1, 0.f);
                v2 = fmaxf(v2, 0.f); v3 = fmaxf(v3, 0.f);
            }
            const size_t o0 = (size_t)r0 * ostride + n0 + cl;
            const size_t o1 = (size_t)(r0 + 8) * ostride + n0 + cl;
            if (mode == 2) {
                *(float2*)(outF + o0) = make_float2(v0, v1);
                *(float2*)(outF + o1) = make_float2(v2, v3);
            } else {
                __half2 h01 = __floats2half2_rn(v0, v1);
                __half2 h23 = __floats2half2_rn(v2, v3);
                *(uint32_t*)(outH + o0) = *(uint32_t*)&h01;
                *(uint32_t*)(outH + o1) = *(uint32_t*)&h23;
            }
        }
    }
}

// ---------------------------------------------------------------------------
// Final layer: out[b, 0..5] = relu(h2[b,:] @ w3 + b3), one warp per row
// ---------------------------------------------------------------------------
__global__ void __launch_bounds__(128) final_fc(const float* __restrict__ h2,
                                                const float* __restrict__ w3,
                                                const float* __restrict__ b3,
                                                float* __restrict__ out) {
    const int wid = threadIdx.x >> 5, lid = threadIdx.x & 31;
    const int row = blockIdx.x * 4 + wid;
    const float* hr = h2 + (size_t)row * D3;
    float acc[NACT] = {0.f, 0.f, 0.f, 0.f, 0.f, 0.f};
    for (int k = lid; k < D3; k += 32) {
        float hv = hr[k];
        #pragma unroll
        for (int j = 0; j < NACT; j++) acc[j] += hv * w3[k * NACT + j];
    }
    #pragma unroll
    for (int off = 16; off > 0; off >>= 1) {
        #pragma unroll
        for (int j = 0; j < NACT; j++)
            acc[j] += __shfl_down_sync(0xFFFFFFFFu, acc[j], off);
    }
    if (lid == 0) {
        #pragma unroll
        for (int j = 0; j < NACT; j++)
            out[(size_t)row * NACT + j] = fmaxf(acc[j] + b3[j], 0.0f);
    }
}

// ---------------------------------------------------------------------------
// Launch
// ---------------------------------------------------------------------------
extern "C" void kernel_launch(void* const* d_in, const int* in_sizes, int n_in,
                              void* d_out, int out_size) {
    (void)in_sizes; (void)n_in; (void)out_size;
    const float* x    = (const float*)d_in[0];
    const float* gpem = (const float*)d_in[1];
    const float* gpew = (const float*)d_in[2];
    const float* gpeb = (const float*)d_in[3];
    const float* gpim = (const float*)d_in[4];
    const float* gpiw = (const float*)d_in[5];
    const float* gpib = (const float*)d_in[6];
    const float* w1   = (const float*)d_in[7];
    const float* b1   = (const float*)d_in[8];
    const float* w2   = (const float*)d_in[9];
    const float* b2   = (const float*)d_in[10];
    const float* w3   = (const float*)d_in[11];
    const float* b3   = (const float*)d_in[12];
    float* out = (float*)d_out;

    void *pAC, *pG, *pH1, *pH2, *pWg, *pWi, *pW1, *pW2;
    cudaGetSymbolAddress(&pAC, g_AC);
    cudaGetSymbolAddress(&pG,  g_G);
    cudaGetSymbolAddress(&pH1, g_H1);
    cudaGetSymbolAddress(&pH2, g_H2);
    cudaGetSymbolAddress(&pWg, g_Wg);
    cudaGetSymbolAddress(&pWi, g_Wi);
    cudaGetSymbolAddress(&pW1, g_W1);
    cudaGetSymbolAddress(&pW2, g_W2);

    __half* AC = (__half*)pAC;
    __half* G  = (__half*)pG;
    __half* H1 = (__half*)pH1;
    float*  H2 = (float*)pH2;

    constexpr int SMEM_192 = OFF_STAGE + STAGES * (16384 + 192 * 128);  // 164864
    constexpr int SMEM_128 = OFF_STAGE + STAGES * (16384 + 128 * 128);  // 132096
    cudaFuncSetAttribute(gemm_h<192>, cudaFuncAttributeMaxDynamicSharedMemorySize, SMEM_192);
    cudaFuncSetAttribute(gemm_h<128>, cudaFuncAttributeMaxDynamicSharedMemorySize, SMEM_128);

    // One fused prep launch (all descriptors via kernel params — capture-safe)
    prep_all<<<dim3(D2 / 32, D1 / 32, 4), 256>>>(
        gpew, gpem,    (__half*)pWg, D1, D1,
        gpiw, gpim,    (__half*)pWi, D2, D1,
        w1,   nullptr, (__half*)pW1, D1, D3,
        w2,   nullptr, (__half*)pW2, D3, D3);
    split_x<<<(BSZ * (D1 / 4) + 255) / 256, 256>>>(x, AC);

    // L1 (gpe): [B,1536] @ Wg^T -> AC cols [1536,3072)
    gemm_h<192><<<dim3(BSZ / BM, D1 / 192), NTHREADS, SMEM_192>>>(
        AC, D2, (__half*)pWg, D1, gpeb, AC + D1, nullptr, D2, D1, 0);
    // L2 (gpi): [B,3072] @ Wi^T -> G
    gemm_h<192><<<dim3(BSZ / BM, D1 / 192), NTHREADS, SMEM_192>>>(
        AC, D2, (__half*)pWi, D2, gpib, G, nullptr, D1, D2, 0);
    // L3: relu(G @ w1) -> H1
    gemm_h<128><<<dim3(BSZ / BM, D3 / 128), NTHREADS, SMEM_128>>>(
        G, D1, (__half*)pW1, D1, b1, H1, nullptr, D3, D1, 1);
    // L4: relu(H1 @ w2) -> H2 (fp32)
    gemm_h<128><<<dim3(BSZ / BM, D3 / 128), NTHREADS, SMEM_128>>>(
        H1, D3, (__half*)pW2, D3, b2, nullptr, H2, D3, D3, 2);
    // L5: tiny fp32 layer
    final_fc<<<BSZ / 4, 128>>>(H2, w3, b3, out);
}

// round 15
// speedup vs baseline: 1.2109x; 1.2109x over previous
#include <cuda_runtime.h>
#include <cuda_fp16.h>
#include <cstdint>

// ---------------------------------------------------------------------------
// Problem dims
// ---------------------------------------------------------------------------
#define BSZ   16384
#define D1    1536    // gpe in / gpe out / gpi out
#define D2    3072    // gpi in (concat)
#define D3    512     // unit3
#define NACT  6

#define BM 128
#define BK 64
#define STAGES 4

// ---------------------------------------------------------------------------
// Helpers (plain sm_103 ISA: cp.async + ldmatrix + mma.sync)
// ---------------------------------------------------------------------------
__device__ __forceinline__ uint32_t smem_u32(const void* p) {
    uint32_t a;
    asm("{ .reg .u64 t; cvta.to.shared.u64 t, %1; cvt.u32.u64 %0, t; }"
        : "=r"(a) : "l"(p));
    return a;
}

#define CP_ASYNC16(dst_u32, src_ptr) \
    asm volatile("cp.async.cg.shared.global [%0], [%1], 16;" \
                 :: "r"(dst_u32), "l"(src_ptr))
#define CP_COMMIT() asm volatile("cp.async.commit_group;")
#define CP_WAIT(n)  asm volatile("cp.async.wait_group %0;" :: "n"(n))

__device__ __forceinline__ void ldsm4(uint32_t* r, uint32_t a) {
    asm volatile("ldmatrix.sync.aligned.m8n8.x4.shared.b16 {%0,%1,%2,%3}, [%4];"
                 : "=r"(r[0]), "=r"(r[1]), "=r"(r[2]), "=r"(r[3]) : "r"(a));
}

__device__ __forceinline__ void mma16816(float* c, const uint32_t* a, const uint32_t* b) {
    asm volatile(
        "mma.sync.aligned.m16n8k16.row.col.f32.f16.f16.f32 "
        "{%0,%1,%2,%3}, {%4,%5,%6,%7}, {%8,%9}, {%0,%1,%2,%3};"
        : "+f"(c[0]), "+f"(c[1]), "+f"(c[2]), "+f"(c[3])
        : "r"(a[0]), "r"(a[1]), "r"(a[2]), "r"(a[3]), "r"(b[0]), "r"(b[1]));
}

#define SW128(o) ((uint32_t)(o) ^ ((((uint32_t)(o)) >> 3) & 0x70))

// ---------------------------------------------------------------------------
// Device scratch (no cudaMalloc allowed)
// ---------------------------------------------------------------------------
__device__ __align__(256) __half g_AC[(size_t)BSZ * D2];   // [B,3072] concat(x, gpe_out)
__device__ __align__(256) __half g_G [(size_t)BSZ * D1];   // gpi_out
__device__ __align__(256) __half g_H1[(size_t)BSZ * D3];
__device__ __align__(256) float  g_H2[(size_t)BSZ * D3];
__device__ __align__(256) __half g_Wg[(size_t)D1 * D1];    // [N][K]
__device__ __align__(256) __half g_Wi[(size_t)D1 * D2];
__device__ __align__(256) __half g_W1[(size_t)D3 * D1];
__device__ __align__(256) __half g_W2[(size_t)D3 * D3];

// ---------------------------------------------------------------------------
// Fused weight prep: tiled coalesced transpose (+ optional mask) -> fp16
// ---------------------------------------------------------------------------
__global__ void __launch_bounds__(256) prep_all(
    const float* W0, const float* M0, __half* O0, int K0, int N0,
    const float* W1p, const float* M1, __half* O1, int K1, int N1,
    const float* W2p, const float* M2, __half* O2, int K2, int N2,
    const float* W3p, const float* M3, __half* O3, int K3, int N3)
{
    const float* W; const float* mask; __half* out; int K, N;
    switch (blockIdx.z) {
        case 0:  W = W0;  mask = M0; out = O0; K = K0; N = N0; break;
        case 1:  W = W1p; mask = M1; out = O1; K = K1; N = N1; break;
        case 2:  W = W2p; mask = M2; out = O2; K = K2; N = N2; break;
        default: W = W3p; mask = M3; out = O3; K = K3; N = N3; break;
    }
    const int k0 = blockIdx.x * 32;
    const int n0 = blockIdx.y * 32;
    if (k0 >= K || n0 >= N) return;

    __shared__ float tile[32][33];
    const int tx = threadIdx.x & 31;
    const int ty = threadIdx.x >> 5;

    #pragma unroll
    for (int i = 0; i < 4; i++) {
        const int k = k0 + ty + i * 8;
        tile[ty + i * 8][tx] = W[(size_t)k * N + n0 + tx];
    }
    __syncthreads();

    #pragma unroll
    for (int i = 0; i < 4; i++) {
        const int n = n0 + ty + i * 8;
        const size_t o = (size_t)n * K + k0 + tx;
        float v = tile[tx][ty + i * 8];
        if (mask) v *= mask[o];
        out[o] = __float2half_rn(v);
    }
}

// x [B][1536] fp32 -> AC cols [0,1536) fp16 with row stride 3072
__global__ void split_x(const float* __restrict__ x, __half* __restrict__ o) {
    int i4 = blockIdx.x * 256 + threadIdx.x;
    const int quads_per_row = D1 / 4;                  // 384
    if (i4 >= BSZ * quads_per_row) return;
    int row = i4 / quads_per_row;
    int c4  = i4 - row * quads_per_row;
    float4 v = ((const float4*)x)[i4];
    size_t off = (size_t)row * D2 + c4 * 4;
    __half2 p0 = __floats2half2_rn(v.x, v.y);
    __half2 p1 = __floats2half2_rn(v.z, v.w);
    *(uint2*)(o + off) = make_uint2(*(uint32_t*)&p0, *(uint32_t*)&p1);
}

// ---------------------------------------------------------------------------
// fp16 GEMM, 256 threads, 8 warps 2x4; warp tile 64 x (BN/4).
// Cross-kt fragment prefetch: ks=0 fragments of kt+1 are loaded BEFORE the
// kt-boundary barrier (enabled by cp.async.wait_group(1) = fill(kt+1) done),
// so the tensor pipe restarts immediately after the barrier.
// mode: 0 = store fp16, 1 = relu + store fp16, 2 = relu + store fp32
// ---------------------------------------------------------------------------
static constexpr int OFF_STAGE = 1024;     // bias lives in [0, BN*4)
static constexpr int ST_A = 0;             // A: 128 rows x 128B = 16KB

template<int BN_T>
__global__ void __launch_bounds__(256, 1)
gemm_h(const __half* __restrict__ A, int lda,
       const __half* __restrict__ B, int ldb,
       const float* __restrict__ bias,
       __half* __restrict__ outH, float* __restrict__ outF,
       int ostride, int K, int mode)
{
    constexpr int WTN = BN_T / 4;          // warp tile N
    constexpr int NJ  = WTN / 8;           // n8-frags per warp
    constexpr int NB  = NJ / 2;            // B ldmatrix.x4 per ks per warp
    constexpr int BROWS = BN_T / 32;       // cp.async row-iters for B
    constexpr int STAGE_BYTES = 16384 + BN_T * 128;

    extern __shared__ char smem[];
    const uint32_t sb = smem_u32(smem);
    const int t = threadIdx.x, wid = t >> 5, lane = t & 31;
    const int wm = wid & 1, wn = wid >> 1;            // 2 x 4 warp grid
    const int m0 = blockIdx.x * BM;
    const int n0 = blockIdx.y * BN_T;

    if (t < BN_T) ((float*)smem)[t] = bias[n0 + t];

    const int chunk = t & 7;               // 16B chunk within 128B row
    const int rset  = t >> 3;              // 0..31

    auto load_stage = [&](int st, int kt) {
        const int k0 = kt * BK;
        const uint32_t stg = sb + OFF_STAGE + st * STAGE_BYTES;
        #pragma unroll
        for (int rr = 0; rr < 4; rr++) {
            const int row = rset + rr * 32;
            const uint32_t so = SW128(row * 128 + chunk * 16);
            CP_ASYNC16(stg + ST_A + so, A + (size_t)(m0 + row) * lda + k0 + chunk * 8);
        }
        #pragma unroll
        for (int rr = 0; rr < BROWS; rr++) {
            const int row = rset + rr * 32;
            const uint32_t so = SW128(row * 128 + chunk * 16);
            CP_ASYNC16(stg + 16384 + so, B + (size_t)(n0 + row) * ldb + k0 + chunk * 8);
        }
    };

    const int KT = K / BK;

    #pragma unroll
    for (int s = 0; s < STAGES - 1; s++) {
        if (s < KT) load_stage(s, s);
        CP_COMMIT();
    }

    float acc[4][NJ][4];
    #pragma unroll
    for (int a = 0; a < 4; a++)
        #pragma unroll
        for (int b = 0; b < NJ; b++)
            #pragma unroll
            for (int c = 0; c < 4; c++) acc[a][b][c] = 0.0f;

    // lane-invariant ldmatrix addressing
    const int rowA_l = wm * 64 + (lane & 15);
    const int kbA_l  = (lane & 16) ? 16 : 0;
    const int rowB_l = wn * WTN + (lane & 7) + ((lane & 16) ? 8 : 0);
    const int kbB_l  = (lane & 8) ? 16 : 0;

    // double-buffered fragments
    uint32_t ah[2][4][4], bh[2][NB][4];

    auto load_frags = [&](uint32_t stg, int ks, int buf) {
        const int kbA = ks * 32 + kbA_l;
        const int kbB = ks * 32 + kbB_l;
        #pragma unroll
        for (int mi = 0; mi < 4; mi++)
            ldsm4(ah[buf][mi], stg + ST_A + SW128((rowA_l + mi * 16) * 128 + kbA));
        #pragma unroll
        for (int bj = 0; bj < NB; bj++)
            ldsm4(bh[buf][bj], stg + 16384 + SW128((rowB_l + bj * 16) * 128 + kbB));
    };

    // prologue: ensure stage 0 resident, preload its ks=0 fragments
    CP_WAIT(2);
    __syncthreads();
    load_frags(sb + OFF_STAGE, 0, 0);

    for (int kt = 0; kt < KT; ++kt) {
        // wait_group(1): fills kt AND kt+1 are complete -> cross-kt prefetch
        // below (reading stage kt+1 at ks==3) is safe. The barrier orders all
        // prior reads of stage (kt+3)%4 (last touched at iter kt-1) before
        // its refill.
        CP_WAIT(1);
        __syncthreads();
        if (kt + STAGES - 1 < KT) load_stage((kt + STAGES - 1) % STAGES, kt + STAGES - 1);
        CP_COMMIT();

        const uint32_t stg  = sb + OFF_STAGE + (kt % STAGES) * STAGE_BYTES;
        const uint32_t nstg = sb + OFF_STAGE + ((kt + 1) % STAGES) * STAGE_BYTES;

        #pragma unroll
        for (int ks = 0; ks < BK / 16; ks++) {
            const int cur = ks & 1;
            if (ks < BK / 16 - 1) load_frags(stg, ks + 1, cur ^ 1);
            else                  load_frags(nstg, 0, cur ^ 1);   // cross-kt prefetch
            #pragma unroll
            for (int mi = 0; mi < 4; mi++) {
                #pragma unroll
                for (int nj = 0; nj < NJ; nj++)
                    mma16816(acc[mi][nj], ah[cur][mi], &bh[cur][nj >> 1][(nj & 1) * 2]);
            }
        }
    }

    // -------------------- epilogue --------------------
    const float* sBias = (const float*)smem;
    const int q  = lane >> 2;
    const int p2 = 2 * (lane & 3);
    #pragma unroll
    for (int mi = 0; mi < 4; mi++) {
        #pragma unroll
        for (int nj = 0; nj < NJ; nj++) {
            const int cl = wn * WTN + nj * 8 + p2;
            const int r0 = m0 + wm * 64 + mi * 16 + q;
            const float bz0 = sBias[cl], bz1 = sBias[cl + 1];
            float v0 = acc[mi][nj][0] + bz0;
            float v1 = acc[mi][nj][1] + bz1;
            float v2 = acc[mi][nj][2] + bz0;
            float v3 = acc[mi][nj][3] + bz1;
            if (mode >= 1) {
                v0 = fmaxf(v0, 0.f); v1 = fmaxf(v1, 0.f);
                v2 = fmaxf(v2, 0.f); v3 = fmaxf(v3, 0.f);
            }
            const size_t o0 = (size_t)r0 * ostride + n0 + cl;
            const size_t o1 = (size_t)(r0 + 8) * ostride + n0 + cl;
            if (mode == 2) {
                *(float2*)(outF + o0) = make_float2(v0, v1);
                *(float2*)(outF + o1) = make_float2(v2, v3);
            } else {
                __half2 h01 = __floats2half2_rn(v0, v1);
                __half2 h23 = __floats2half2_rn(v2, v3);
                *(uint32_t*)(outH + o0) = *(uint32_t*)&h01;
                *(uint32_t*)(outH + o1) = *(uint32_t*)&h23;
            }
        }
    }
}

// ---------------------------------------------------------------------------
// Final layer: out[b, 0..5] = relu(h2[b,:] @ w3 + b3), one warp per row
// ---------------------------------------------------------------------------
__global__ void __launch_bounds__(128) final_fc(const float* __restrict__ h2,
                                                const float* __restrict__ w3,
                                                const float* __restrict__ b3,
                                                float* __restrict__ out) {
    const int wid = threadIdx.x >> 5, lid = threadIdx.x & 31;
    const int row = blockIdx.x * 4 + wid;
    const float* hr = h2 + (size_t)row * D3;
    float acc[NACT] = {0.f, 0.f, 0.f, 0.f, 0.f, 0.f};
    for (int k = lid; k < D3; k += 32) {
        float hv = hr[k];
        #pragma unroll
        for (int j = 0; j < NACT; j++) acc[j] += hv * w3[k * NACT + j];
    }
    #pragma unroll
    for (int off = 16; off > 0; off >>= 1) {
        #pragma unroll
        for (int j = 0; j < NACT; j++)
            acc[j] += __shfl_down_sync(0xFFFFFFFFu, acc[j], off);
    }
    if (lid == 0) {
        #pragma unroll
        for (int j = 0; j < NACT; j++)
            out[(size_t)row * NACT + j] = fmaxf(acc[j] + b3[j], 0.0f);
    }
}

// ---------------------------------------------------------------------------
// Launch
// ---------------------------------------------------------------------------
extern "C" void kernel_launch(void* const* d_in, const int* in_sizes, int n_in,
                              void* d_out, int out_size) {
    (void)in_sizes; (void)n_in; (void)out_size;
    const float* x    = (const float*)d_in[0];
    const float* gpem = (const float*)d_in[1];
    const float* gpew = (const float*)d_in[2];
    const float* gpeb = (const float*)d_in[3];
    const float* gpim = (const float*)d_in[4];
    const float* gpiw = (const float*)d_in[5];
    const float* gpib = (const float*)d_in[6];
    const float* w1   = (const float*)d_in[7];
    const float* b1   = (const float*)d_in[8];
    const float* w2   = (const float*)d_in[9];
    const float* b2   = (const float*)d_in[10];
    const float* w3   = (const float*)d_in[11];
    const float* b3   = (const float*)d_in[12];
    float* out = (float*)d_out;

    void *pAC, *pG, *pH1, *pH2, *pWg, *pWi, *pW1, *pW2;
    cudaGetSymbolAddress(&pAC, g_AC);
    cudaGetSymbolAddress(&pG,  g_G);
    cudaGetSymbolAddress(&pH1, g_H1);
    cudaGetSymbolAddress(&pH2, g_H2);
    cudaGetSymbolAddress(&pWg, g_Wg);
    cudaGetSymbolAddress(&pWi, g_Wi);
    cudaGetSymbolAddress(&pW1, g_W1);
    cudaGetSymbolAddress(&pW2, g_W2);

    __half* AC = (__half*)pAC;
    __half* G  = (__half*)pG;
    __half* H1 = (__half*)pH1;
    float*  H2 = (float*)pH2;

    constexpr int SMEM_192 = OFF_STAGE + STAGES * (16384 + 192 * 128);  // 164864
    constexpr int SMEM_128 = OFF_STAGE + STAGES * (16384 + 128 * 128);  // 132096
    cudaFuncSetAttribute(gemm_h<192>, cudaFuncAttributeMaxDynamicSharedMemorySize, SMEM_192);
    cudaFuncSetAttribute(gemm_h<128>, cudaFuncAttributeMaxDynamicSharedMemorySize, SMEM_128);

    // One fused prep launch (all descriptors via kernel params — capture-safe)
    prep_all<<<dim3(D2 / 32, D1 / 32, 4), 256>>>(
        gpew, gpem,    (__half*)pWg, D1, D1,
        gpiw, gpim,    (__half*)pWi, D2, D1,
        w1,   nullptr, (__half*)pW1, D1, D3,
        w2,   nullptr, (__half*)pW2, D3, D3);
    split_x<<<(BSZ * (D1 / 4) + 255) / 256, 256>>>(x, AC);

    // L1 (gpe): [B,1536] @ Wg^T -> AC cols [1536,3072)
    gemm_h<192><<<dim3(BSZ / BM, D1 / 192), 256, SMEM_192>>>(
        AC, D2, (__half*)pWg, D1, gpeb, AC + D1, nullptr, D2, D1, 0);
    // L2 (gpi): [B,3072] @ Wi^T -> G
    gemm_h<192><<<dim3(BSZ / BM, D1 / 192), 256, SMEM_192>>>(
        AC, D2, (__half*)pWi, D2, gpib, G, nullptr, D1, D2, 0);
    // L3: relu(G @ w1) -> H1
    gemm_h<128><<<dim3(BSZ / BM, D3 / 128), 256, SMEM_128>>>(
        G, D1, (__half*)pW1, D1, b1, H1, nullptr, D3, D1, 1);
    // L4: relu(H1 @ w2) -> H2 (fp32)
    gemm_h<128><<<dim3(BSZ / BM, D3 / 128), 256, SMEM_128>>>(
        H1, D3, (__half*)pW2, D3, b2, nullptr, H2, D3, D3, 2);
    // L5: tiny fp32 layer
    final_fc<<<BSZ / 4, 128>>>(H2, w3, b3, out);
}